// round 12
// baseline (speedup 1.0000x reference)
#include <cuda_runtime.h>
#include <cuda_fp16.h>
#include <cstdint>

#define B_DIM 2048
#define M_DIM 64
#define F_DIM 512
#define U_DIM 512
#define LDX (M_DIM * F_DIM)
#define LDO (M_DIM * U_DIM)

#define BM 128
#define BN 128
#define BK 64
#define THREADS 256            // 8 warps: 4 (M) x 2 (N), warp tile 32x64
#define KITERS (F_DIM / BK)    // 8

#define ROWB 144                             // bytes per smem row (64 halves + 8 pad)
#define TILE_BYTES (128 * ROWB)              // 18432 B per A or B tile
#define STAGE_BYTES (2 * TILE_BYTES)         // 36864 B
#define STAGES 3
#define DYN_SMEM (STAGES * STAGE_BYTES)      // 110592 B -> 2 CTAs/SM

__device__ __half g_Wh[(size_t)M_DIM * F_DIM * U_DIM];   // W^T fp16: [m][u][k]

// ---------------- helpers ----------------
static __device__ __forceinline__ uint32_t cvta_smem(const void* p) {
    uint32_t a;
    asm("{ .reg .u64 t; cvta.to.shared.u64 t, %1; cvt.u32.u64 %0, t; }" : "=r"(a) : "l"(p));
    return a;
}
static __device__ __forceinline__ void cp_async16(uint32_t smem_addr, const void* gptr) {
    asm volatile("cp.async.cg.shared.global [%0], [%1], 16;" :: "r"(smem_addr), "l"(gptr) : "memory");
}
static __device__ __forceinline__ void cp_commit() {
    asm volatile("cp.async.commit_group;" ::: "memory");
}
template <int N>
static __device__ __forceinline__ void cp_wait() {
    asm volatile("cp.async.wait_group %0;" :: "n"(N) : "memory");
}
static __device__ __forceinline__ void ldsm_x4(uint32_t addr, uint32_t* r) {
    asm volatile("ldmatrix.sync.aligned.m8n8.x4.shared.b16 {%0,%1,%2,%3}, [%4];"
                 : "=r"(r[0]), "=r"(r[1]), "=r"(r[2]), "=r"(r[3]) : "r"(addr));
}
static __device__ __forceinline__ void mma_f16(float* c, const uint32_t* a, const uint32_t* b) {
    asm volatile(
        "mma.sync.aligned.m16n8k16.row.col.f32.f16.f16.f32 "
        "{%0,%1,%2,%3}, {%4,%5,%6,%7}, {%8,%9}, {%0,%1,%2,%3};"
        : "+f"(c[0]), "+f"(c[1]), "+f"(c[2]), "+f"(c[3])
        : "r"(a[0]), "r"(a[1]), "r"(a[2]), "r"(a[3]), "r"(b[0]), "r"(b[1]));
}
static __device__ __forceinline__ void sts64(uint32_t addr, uint32_t lo, uint32_t hi) {
    asm volatile("st.shared.v2.b32 [%0], {%1,%2};" :: "r"(addr), "r"(lo), "r"(hi) : "memory");
}
static __device__ __forceinline__ void cvt_f4_h4(float4 v, uint32_t& lo, uint32_t& hi) {
    __half2 a = __floats2half2_rn(v.x, v.y);
    __half2 b = __floats2half2_rn(v.z, v.w);
    lo = *(uint32_t*)&a; hi = *(uint32_t*)&b;
}

// ---------------- prep: W transpose + fp16: g_Wh[m][u][k] = (half)W[m][k][u] ----------------
__global__ void transpose_W_kernel(const float* __restrict__ W) {
    __shared__ float t[32][33];
    const int m = blockIdx.z;
    const int u0 = blockIdx.x * 32, k0 = blockIdx.y * 32;
    const int tx = threadIdx.x, ty = threadIdx.y;
    const float* Wm = W + (size_t)m * F_DIM * U_DIM;
    __half* Wtm = g_Wh + (size_t)m * F_DIM * U_DIM;
#pragma unroll
    for (int i = 0; i < 32; i += 8)
        t[ty + i][tx] = Wm[(size_t)(k0 + ty + i) * U_DIM + u0 + tx];
    __syncthreads();
#pragma unroll
    for (int i = 0; i < 32; i += 8)
        Wtm[(size_t)(u0 + ty + i) * F_DIM + k0 + tx] = __float2half_rn(t[tx][ty + i]);
}

// ---------------- main GEMM: fp16 mma.sync, BK=64, fused A fp32->fp16 staging ----------------
__global__ __launch_bounds__(THREADS, 2)
void pd_mma_f16(const float* __restrict__ x,
                const float* __restrict__ bias,
                float* __restrict__ out) {
    extern __shared__ __align__(16) char smem[];
    const uint32_t smemAddr = cvta_smem(smem);

    const int tid  = threadIdx.x;
    const int wid  = tid >> 5;
    const int lane = tid & 31;
    const int warpM = wid >> 1;         // 0..3
    const int warpN = wid & 1;          // 0..1
    const int g = lane >> 2;            // groupID
    const int t = lane & 3;             // thread-in-group
    const int quad = lane >> 3;         // ldmatrix address quad
    const int rl   = lane & 7;
    const int rot  = (wid & 1) * 2;     // ks rotation: desync LDSM bursts

    const int bn = blockIdx.x, bm = blockIdx.y, m = blockIdx.z;
    const int rowBase = bm * BM;
    const int colBase = bn * BN;

    const float*  Xm  = x + (size_t)m * F_DIM;
    const __half* Wtm = g_Wh + (size_t)m * F_DIM * U_DIM;

    // ---- A fill (fp32 gmem -> cvt -> smem): 128 rows x 16 float4 = 2048 chunks; 8/thread ----
    // j-th chunk: e = j*256 + tid; r = e>>4 (row), c = e&15 (float4-in-row).
    // r steps by 16 per j, c fixed -> single base pointer + j*16*LDX stride.
    const int aR0 = tid >> 4, aC = tid & 15;
    const float* aFillSrc = Xm + (size_t)(rowBase + aR0) * LDX + aC * 4;
    const uint32_t aFillDst = (uint32_t)(aR0 * ROWB + aC * 8);

    // ---- B staging (cp.async fp16): 128 rows x 8 chunks(16B); 4/thread, r steps 32 ----
    const int bR0 = tid >> 3, bC = tid & 7;
    const __half* bFillSrc = Wtm + (size_t)(colBase + bR0) * F_DIM + bC * 8;
    const uint32_t bFillDst = (uint32_t)(bR0 * ROWB + bC * 16) + TILE_BYTES;

    auto fill_A = [&](uint32_t stageOff, int k0) {     // full fill (prologue)
#pragma unroll
        for (int j = 0; j < 8; ++j) {
            float4 v = *(const float4*)(aFillSrc + (size_t)j * 16 * LDX + k0);
            uint32_t lo, hi; cvt_f4_h4(v, lo, hi);
            sts64(smemAddr + stageOff + aFillDst + j * 16 * ROWB, lo, hi);
        }
    };
    auto issue_B = [&](uint32_t stageOff, int k0) {
#pragma unroll
        for (int j = 0; j < 4; ++j)
            cp_async16(smemAddr + stageOff + bFillDst + j * 32 * ROWB, bFillSrc + (size_t)j * 32 * F_DIM + k0);
        cp_commit();
    };

    // ---- ldmatrix per-lane offsets ----
    const uint32_t aLaneOff =
        (uint32_t)((warpM * 32 + (quad & 1) * 8 + rl) * ROWB + (quad >> 1) * 16);
    const uint32_t bLaneOff =
        (uint32_t)((warpN * 64 + (quad >> 1) * 8 + rl) * ROWB + (quad & 1) * 16) + TILE_BYTES;

    float acc[2][8][4];
#pragma unroll
    for (int mi = 0; mi < 2; ++mi)
#pragma unroll
        for (int ni = 0; ni < 8; ++ni)
#pragma unroll
            for (int c = 0; c < 4; ++c) acc[mi][ni][c] = 0.0f;

    // ---- prologue: stages 0,1 ----
    issue_B(0, 0);
    issue_B(STAGE_BYTES, BK);
    fill_A(0, 0);
    fill_A(STAGE_BYTES, BK);

    uint32_t compOff  = 0;
    uint32_t issueOff = 2 * STAGE_BYTES;

    for (int it = 0; it < KITERS; ++it) {
        // Pending B groups: stages it, it+1. wait<1> -> B(it) arrived.
        cp_wait<1>();
        // Barrier: stage it fully visible (B cp.async + A STS from iter it-1);
        // all warps done computing it-1, so refilling buffer (it+2)%3 is safe.
        __syncthreads();

        const uint32_t aA = smemAddr + compOff + aLaneOff;
        const uint32_t bA = smemAddr + compOff + bLaneOff;

        const bool fill = (it + 2 < KITERS);
        const int fillK = (it + 2) * BK;
        float4 av[4];

#pragma unroll
        for (int kk = 0; kk < 4; ++kk) {
            const int ks = (kk + rot) & 3;           // warp-parity rotated k16-chunk
            const uint32_t ko = (uint32_t)(ks * 32); // 16 halves = 32 B

            uint32_t af[2][4], bf[4][4];
            ldsm_x4(aA + ko,             af[0]);
            ldsm_x4(aA + 16 * ROWB + ko, af[1]);     // +16 rows
            ldsm_x4(bA + ko,             bf[0]);     // n-groups 0,1
            ldsm_x4(bA + 16 * ROWB + ko, bf[1]);     // n-groups 2,3
#pragma unroll
            for (int p = 0; p < 2; ++p) {
#pragma unroll
                for (int mi = 0; mi < 2; ++mi) {
                    mma_f16(acc[mi][2 * p],     af[mi], &bf[p][0]);
                    mma_f16(acc[mi][2 * p + 1], af[mi], &bf[p][2]);
                }
            }
            ldsm_x4(bA + 32 * ROWB + ko, bf[2]);     // n-groups 4,5
            ldsm_x4(bA + 48 * ROWB + ko, bf[3]);     // n-groups 6,7

            // ---- staged A fill + B issue for stage it+2, spread across kk phases ----
            if (kk == 0) {
                if (fill) {
#pragma unroll
                    for (int j = 0; j < 4; ++j)
                        av[j] = *(const float4*)(aFillSrc + (size_t)j * 16 * LDX + fillK);
                }
            } else if (kk == 1) {
                if (fill) {
#pragma unroll
                    for (int j = 0; j < 4; ++j) {
                        uint32_t lo, hi; cvt_f4_h4(av[j], lo, hi);
                        sts64(smemAddr + issueOff + aFillDst + j * 16 * ROWB, lo, hi);
                    }
                    issue_B(issueOff, fillK);
                } else {
                    cp_commit();                     // keep group accounting aligned
                }
            } else if (kk == 2) {
                if (fill) {
#pragma unroll
                    for (int j = 0; j < 4; ++j)
                        av[j] = *(const float4*)(aFillSrc + (size_t)(j + 4) * 16 * LDX + fillK);
                }
            } else {
                if (fill) {
#pragma unroll
                    for (int j = 0; j < 4; ++j) {
                        uint32_t lo, hi; cvt_f4_h4(av[j], lo, hi);
                        sts64(smemAddr + issueOff + aFillDst + (j + 4) * 16 * ROWB, lo, hi);
                    }
                }
            }

#pragma unroll
            for (int p = 2; p < 4; ++p) {
#pragma unroll
                for (int mi = 0; mi < 2; ++mi) {
                    mma_f16(acc[mi][2 * p],     af[mi], &bf[p][0]);
                    mma_f16(acc[mi][2 * p + 1], af[mi], &bf[p][2]);
                }
            }
        }

        compOff += STAGE_BYTES;  if (compOff  == DYN_SMEM) compOff  = 0;
        issueOff += STAGE_BYTES; if (issueOff == DYN_SMEM) issueOff = 0;
    }

    // ---------------- epilogue: bias + relu + store ----------------
    const float* bm_bias = bias + (size_t)m * U_DIM + colBase + warpN * 64;
#pragma unroll
    for (int mi = 0; mi < 2; ++mi) {
        const int r0 = rowBase + warpM * 32 + mi * 16 + g;
        float* o0 = out + (size_t)r0 * LDO + (size_t)m * U_DIM + colBase + warpN * 64;
        float* o1 = o0 + (size_t)8 * LDO;
#pragma unroll
        for (int ni = 0; ni < 8; ++ni) {
            const int c = ni * 8 + t * 2;
            const float b0 = bm_bias[c], b1 = bm_bias[c + 1];
            float2 v0, v1;
            v0.x = fmaxf(acc[mi][ni][0] + b0, 0.0f);
            v0.y = fmaxf(acc[mi][ni][1] + b1, 0.0f);
            v1.x = fmaxf(acc[mi][ni][2] + b0, 0.0f);
            v1.y = fmaxf(acc[mi][ni][3] + b1, 0.0f);
            *(float2*)(o0 + c) = v0;
            *(float2*)(o1 + c) = v1;
        }
    }
}

// ---------------- launch ----------------
extern "C" void kernel_launch(void* const* d_in, const int* in_sizes, int n_in,
                              void* d_out, int out_size) {
    const float* x    = (const float*)d_in[0];
    const float* W    = (const float*)d_in[1];
    const float* bias = (const float*)d_in[2];
    float* out        = (float*)d_out;

    dim3 tg(U_DIM / 32, F_DIM / 32, M_DIM);   // (16,16,64)
    transpose_W_kernel<<<tg, dim3(32, 8)>>>(W);

    cudaFuncSetAttribute(pd_mma_f16, cudaFuncAttributeMaxDynamicSharedMemorySize, DYN_SMEM);
    dim3 grid(U_DIM / BN, B_DIM / BM, M_DIM);  // (4,16,64) = 4096 CTAs
    pd_mma_f16<<<grid, THREADS, DYN_SMEM>>>(x, bias, out);
}

// round 13
// speedup vs baseline: 1.0241x; 1.0241x over previous
#include <cuda_runtime.h>
#include <cuda_fp16.h>
#include <cstdint>

#define B_DIM 2048
#define M_DIM 64
#define F_DIM 512
#define U_DIM 512
#define LDX (M_DIM * F_DIM)
#define LDO (M_DIM * U_DIM)

#define BM 128
#define BN 128
#define BK 64
#define THREADS 256            // 8 warps: 4 (M) x 2 (N), warp tile 32x64
#define KITERS (F_DIM / BK)    // 8

#define ROWB 144                             // bytes per smem row (64 halves + 8 pad)
#define TILE_BYTES (128 * ROWB)              // 18432 B per A or B tile
#define STAGE_BYTES (2 * TILE_BYTES)         // 36864 B
#define STAGES 3
#define DYN_SMEM (STAGES * STAGE_BYTES)      // 110592 B -> 2 CTAs/SM

__device__ __half g_Wh[(size_t)M_DIM * F_DIM * U_DIM];   // W^T fp16: [m][u][k]

// ---------------- helpers ----------------
static __device__ __forceinline__ uint32_t cvta_smem(const void* p) {
    uint32_t a;
    asm("{ .reg .u64 t; cvta.to.shared.u64 t, %1; cvt.u32.u64 %0, t; }" : "=r"(a) : "l"(p));
    return a;
}
static __device__ __forceinline__ void cp_async16(uint32_t smem_addr, const void* gptr) {
    asm volatile("cp.async.cg.shared.global [%0], [%1], 16;" :: "r"(smem_addr), "l"(gptr) : "memory");
}
static __device__ __forceinline__ void cp_commit() {
    asm volatile("cp.async.commit_group;" ::: "memory");
}
template <int N>
static __device__ __forceinline__ void cp_wait() {
    asm volatile("cp.async.wait_group %0;" :: "n"(N) : "memory");
}
static __device__ __forceinline__ void ldsm_x4(uint32_t addr, uint32_t* r) {
    asm volatile("ldmatrix.sync.aligned.m8n8.x4.shared.b16 {%0,%1,%2,%3}, [%4];"
                 : "=r"(r[0]), "=r"(r[1]), "=r"(r[2]), "=r"(r[3]) : "r"(addr));
}
static __device__ __forceinline__ void mma_f16(float* c, const uint32_t* a, const uint32_t* b) {
    asm volatile(
        "mma.sync.aligned.m16n8k16.row.col.f32.f16.f16.f32 "
        "{%0,%1,%2,%3}, {%4,%5,%6,%7}, {%8,%9}, {%0,%1,%2,%3};"
        : "+f"(c[0]), "+f"(c[1]), "+f"(c[2]), "+f"(c[3])
        : "r"(a[0]), "r"(a[1]), "r"(a[2]), "r"(a[3]), "r"(b[0]), "r"(b[1]));
}
static __device__ __forceinline__ void sts64(uint32_t addr, uint32_t lo, uint32_t hi) {
    asm volatile("st.shared.v2.b32 [%0], {%1,%2};" :: "r"(addr), "r"(lo), "r"(hi) : "memory");
}
static __device__ __forceinline__ void cvt_f4_h4(float4 v, uint32_t& lo, uint32_t& hi) {
    __half2 a = __floats2half2_rn(v.x, v.y);
    __half2 b = __floats2half2_rn(v.z, v.w);
    lo = *(uint32_t*)&a; hi = *(uint32_t*)&b;
}

// ---------------- prep: W transpose + fp16: g_Wh[m][u][k] = (half)W[m][k][u] ----------------
__global__ void transpose_W_kernel(const float* __restrict__ W) {
    __shared__ float t[32][33];
    const int m = blockIdx.z;
    const int u0 = blockIdx.x * 32, k0 = blockIdx.y * 32;
    const int tx = threadIdx.x, ty = threadIdx.y;
    const float* Wm = W + (size_t)m * F_DIM * U_DIM;
    __half* Wtm = g_Wh + (size_t)m * F_DIM * U_DIM;
#pragma unroll
    for (int i = 0; i < 32; i += 8)
        t[ty + i][tx] = Wm[(size_t)(k0 + ty + i) * U_DIM + u0 + tx];
    __syncthreads();
#pragma unroll
    for (int i = 0; i < 32; i += 8)
        Wtm[(size_t)(u0 + ty + i) * F_DIM + k0 + tx] = __float2half_rn(t[tx][ty + i]);
}

// ---------------- main GEMM: fp16 mma.sync, BK=64, fused A fp32->fp16 staging ----------------
__global__ __launch_bounds__(THREADS, 2)
void pd_mma_f16(const float* __restrict__ x,
                const float* __restrict__ bias,
                float* __restrict__ out) {
    extern __shared__ __align__(16) char smem[];
    const uint32_t smemAddr = cvta_smem(smem);

    const int tid  = threadIdx.x;
    const int wid  = tid >> 5;
    const int lane = tid & 31;
    const int warpM = wid >> 1;         // 0..3
    const int warpN = wid & 1;          // 0..1
    const int g = lane >> 2;            // groupID
    const int t = lane & 3;             // thread-in-group
    const int quad = lane >> 3;         // ldmatrix address quad
    const int rl   = lane & 7;
    const int rot  = (wid & 1) * 2;     // ks rotation: desync LDSM bursts

    const int bn = blockIdx.x, bm = blockIdx.y, m = blockIdx.z;
    const int rowBase = bm * BM;
    const int colBase = bn * BN;

    const float*  Xm  = x + (size_t)m * F_DIM;
    const __half* Wtm = g_Wh + (size_t)m * F_DIM * U_DIM;

    // ---- A fill (fp32 gmem -> cvt -> smem): 128 rows x 16 float4 = 2048 chunks; 8/thread ----
    const int aR0 = tid >> 4, aC = tid & 15;
    const float* aFillSrc = Xm + (size_t)(rowBase + aR0) * LDX + aC * 4;
    const uint32_t aFillDst = (uint32_t)(aR0 * ROWB + aC * 8);

    // ---- B staging (cp.async fp16): 128 rows x 8 chunks(16B); 4/thread, r steps 32 ----
    const int bR0 = tid >> 3, bC = tid & 7;
    const __half* bFillSrc = Wtm + (size_t)(colBase + bR0) * F_DIM + bC * 8;
    const uint32_t bFillDst = (uint32_t)(bR0 * ROWB + bC * 16) + TILE_BYTES;

    auto fill_A = [&](uint32_t stageOff, int k0) {     // full fill (prologue)
#pragma unroll
        for (int j = 0; j < 8; ++j) {
            float4 v = *(const float4*)(aFillSrc + (size_t)j * 16 * LDX + k0);
            uint32_t lo, hi; cvt_f4_h4(v, lo, hi);
            sts64(smemAddr + stageOff + aFillDst + j * 16 * ROWB, lo, hi);
        }
    };
    auto issue_B = [&](uint32_t stageOff, int k0) {
#pragma unroll
        for (int j = 0; j < 4; ++j)
            cp_async16(smemAddr + stageOff + bFillDst + j * 32 * ROWB, bFillSrc + (size_t)j * 32 * F_DIM + k0);
        cp_commit();
    };

    // ---- ldmatrix per-lane offsets ----
    const uint32_t aLaneOff =
        (uint32_t)((warpM * 32 + (quad & 1) * 8 + rl) * ROWB + (quad >> 1) * 16);
    const uint32_t bLaneOff =
        (uint32_t)((warpN * 64 + (quad >> 1) * 8 + rl) * ROWB + (quad & 1) * 16) + TILE_BYTES;

    float acc[2][8][4];
#pragma unroll
    for (int mi = 0; mi < 2; ++mi)
#pragma unroll
        for (int ni = 0; ni < 8; ++ni)
#pragma unroll
            for (int c = 0; c < 4; ++c) acc[mi][ni][c] = 0.0f;

    // ---- prologue: stages 0,1 ----
    issue_B(0, 0);
    issue_B(STAGE_BYTES, BK);
    fill_A(0, 0);
    fill_A(STAGE_BYTES, BK);

    uint32_t compOff  = 0;
    uint32_t issueOff = 2 * STAGE_BYTES;

    for (int it = 0; it < KITERS; ++it) {
        // Pending B groups: stages it, it+1. wait<1> -> B(it) arrived.
        cp_wait<1>();
        // Barrier: stage it fully visible (B cp.async + A STS from iter it-1);
        // all warps done computing it-1, so refilling buffer (it+2)%3 is safe.
        __syncthreads();

        const uint32_t aA = smemAddr + compOff + aLaneOff;
        const uint32_t bA = smemAddr + compOff + bLaneOff;

        const bool fill = (it + 2 < KITERS);
        const int fillK = (it + 2) * BK;
        float4 av[4];

        // ---- A LDG batch 0 issued IMMEDIATELY after barrier: consumed at kk1
        //      (~2 kk-phases of slack to cover L2/DRAM latency) ----
        if (fill) {
#pragma unroll
            for (int j = 0; j < 4; ++j)
                av[j] = *(const float4*)(aFillSrc + (size_t)j * 16 * LDX + fillK);
        }

#pragma unroll
        for (int kk = 0; kk < 4; ++kk) {
            const int ks = (kk + rot) & 3;           // warp-parity rotated k16-chunk
            const uint32_t ko = (uint32_t)(ks * 32); // 16 halves = 32 B

            uint32_t af[2][4], bf[4][4];
            ldsm_x4(aA + ko,             af[0]);
            ldsm_x4(aA + 16 * ROWB + ko, af[1]);     // +16 rows
            ldsm_x4(bA + ko,             bf[0]);     // n-groups 0,1
            ldsm_x4(bA + 16 * ROWB + ko, bf[1]);     // n-groups 2,3
#pragma unroll
            for (int p = 0; p < 2; ++p) {
#pragma unroll
                for (int mi = 0; mi < 2; ++mi) {
                    mma_f16(acc[mi][2 * p],     af[mi], &bf[p][0]);
                    mma_f16(acc[mi][2 * p + 1], af[mi], &bf[p][2]);
                }
            }
            ldsm_x4(bA + 32 * ROWB + ko, bf[2]);     // n-groups 4,5
            ldsm_x4(bA + 48 * ROWB + ko, bf[3]);     // n-groups 6,7

            // ---- staged fill for stage it+2 ----
            if (kk == 1) {
                if (fill) {
                    // consume batch 0 (loaded pre-loop), then issue batch 1 LDGs
#pragma unroll
                    for (int j = 0; j < 4; ++j) {
                        uint32_t lo, hi; cvt_f4_h4(av[j], lo, hi);
                        sts64(smemAddr + issueOff + aFillDst + j * 16 * ROWB, lo, hi);
                    }
#pragma unroll
                    for (int j = 0; j < 4; ++j)
                        av[j] = *(const float4*)(aFillSrc + (size_t)(j + 4) * 16 * LDX + fillK);
                    issue_B(issueOff, fillK);
                } else {
                    cp_commit();                     // keep group accounting aligned
                }
            } else if (kk == 3) {
                if (fill) {
                    // consume batch 1 (loaded at kk1): ~2 phases of slack
#pragma unroll
                    for (int j = 0; j < 4; ++j) {
                        uint32_t lo, hi; cvt_f4_h4(av[j], lo, hi);
                        sts64(smemAddr + issueOff + aFillDst + (j + 4) * 16 * ROWB, lo, hi);
                    }
                }
            }

#pragma unroll
            for (int p = 2; p < 4; ++p) {
#pragma unroll
                for (int mi = 0; mi < 2; ++mi) {
                    mma_f16(acc[mi][2 * p],     af[mi], &bf[p][0]);
                    mma_f16(acc[mi][2 * p + 1], af[mi], &bf[p][2]);
                }
            }
        }

        compOff += STAGE_BYTES;  if (compOff  == DYN_SMEM) compOff  = 0;
        issueOff += STAGE_BYTES; if (issueOff == DYN_SMEM) issueOff = 0;
    }

    // ---------------- epilogue: bias + relu + store ----------------
    const float* bm_bias = bias + (size_t)m * U_DIM + colBase + warpN * 64;
#pragma unroll
    for (int mi = 0; mi < 2; ++mi) {
        const int r0 = rowBase + warpM * 32 + mi * 16 + g;
        float* o0 = out + (size_t)r0 * LDO + (size_t)m * U_DIM + colBase + warpN * 64;
        float* o1 = o0 + (size_t)8 * LDO;
#pragma unroll
        for (int ni = 0; ni < 8; ++ni) {
            const int c = ni * 8 + t * 2;
            const float b0 = bm_bias[c], b1 = bm_bias[c + 1];
            float2 v0, v1;
            v0.x = fmaxf(acc[mi][ni][0] + b0, 0.0f);
            v0.y = fmaxf(acc[mi][ni][1] + b1, 0.0f);
            v1.x = fmaxf(acc[mi][ni][2] + b0, 0.0f);
            v1.y = fmaxf(acc[mi][ni][3] + b1, 0.0f);
            *(float2*)(o0 + c) = v0;
            *(float2*)(o1 + c) = v1;
        }
    }
}

// ---------------- launch ----------------
extern "C" void kernel_launch(void* const* d_in, const int* in_sizes, int n_in,
                              void* d_out, int out_size) {
    const float* x    = (const float*)d_in[0];
    const float* W    = (const float*)d_in[1];
    const float* bias = (const float*)d_in[2];
    float* out        = (float*)d_out;

    dim3 tg(U_DIM / 32, F_DIM / 32, M_DIM);   // (16,16,64)
    transpose_W_kernel<<<tg, dim3(32, 8)>>>(W);

    cudaFuncSetAttribute(pd_mma_f16, cudaFuncAttributeMaxDynamicSharedMemorySize, DYN_SMEM);
    dim3 grid(U_DIM / BN, B_DIM / BM, M_DIM);  // (4,16,64) = 4096 CTAs
    pd_mma_f16<<<grid, THREADS, DYN_SMEM>>>(x, bias, out);
}